// round 11
// baseline (speedup 1.0000x reference)
#include <cuda_runtime.h>
#include <cuda_bf16.h>
#include <cuda_fp16.h>
#include <math.h>

#define NN 100000
#define EE 1600000
#define F_IN 1433
#define DD 64
#define DEPTH 3
#define ALPHA 0.9f
#define KC_EMB 90   // ceil(1433/16)

// ---------------- scratch (static device globals) ----------------
__device__ float    g_x0[NN * DD];
__device__ float    g_x [NN * DD];
__device__ float    g_agg[NN * DD];
__device__ float    g_q [NN * DD];
__device__ unsigned g_k2[NN * 32];   // half2-packed k rows (32 x half2 = 64 cols)
__device__ unsigned g_v2[NN * 32];   // half2-packed v rows
__device__ int      g_deg[NN];
__device__ int      g_off[NN + 1];
__device__ int      g_pos[NN];
__device__ int      g_csr[EE];
__device__ uint4    g_Bemb[KC_EMB * 256];  // packed split-bf16 emb weight
__device__ uint4    g_Bw[12 * 1024];       // q,k,v,o x 3 layers (K=64 -> KC=4)

// ---------------- helpers ----------------
__device__ __forceinline__ void split2(float x, float y, unsigned& hi, unsigned& lo) {
    __nv_bfloat162 h = __floats2bfloat162_rn(x, y);
    float rx = x - __low2float(h);
    float ry = y - __high2float(h);
    __nv_bfloat162 l = __floats2bfloat162_rn(rx, ry);
    hi = *reinterpret_cast<unsigned*>(&h);
    lo = *reinterpret_cast<unsigned*>(&l);
}

__device__ __forceinline__ void mma16816(float* c, const unsigned* a,
                                         unsigned b0, unsigned b1) {
    asm volatile(
        "mma.sync.aligned.m16n8k16.row.col.f32.bf16.bf16.f32 "
        "{%0,%1,%2,%3},{%4,%5,%6,%7},{%8,%9},{%0,%1,%2,%3};\n"
        : "+f"(c[0]), "+f"(c[1]), "+f"(c[2]), "+f"(c[3])
        : "r"(a[0]), "r"(a[1]), "r"(a[2]), "r"(a[3]), "r"(b0), "r"(b1));
}

__device__ __forceinline__ float2 h2f2(unsigned w) {
    return __half22float2(*reinterpret_cast<__half2*>(&w));
}

// ---------------- B packing ----------------
__global__ void pack_b_kernel(const float* __restrict__ B, uint4* __restrict__ out,
                              int K, int KC) {
    int idx = blockIdx.x * blockDim.x + threadIdx.x;
    if (idx >= KC * 256) return;
    int lane = idx & 31, nt = (idx >> 5) & 7, kc = idx >> 8;
    int col = nt * 8 + (lane >> 2);
    int kr = kc * 16 + (lane & 3) * 2;
    float f0 = (kr     < K) ? B[(kr    ) * 64 + col] : 0.f;
    float f1 = (kr + 1 < K) ? B[(kr + 1) * 64 + col] : 0.f;
    float f2 = (kr + 8 < K) ? B[(kr + 8) * 64 + col] : 0.f;
    float f3 = (kr + 9 < K) ? B[(kr + 9) * 64 + col] : 0.f;
    unsigned h0, l0, h1, l1;
    split2(f0, f1, h0, l0);
    split2(f2, f3, h1, l1);
    out[idx] = make_uint4(h0, h1, l0, l1);
}

__global__ void pack_w_kernel(const float* __restrict__ Wq, const float* __restrict__ Wk,
                              const float* __restrict__ Wv, const float* __restrict__ Wo,
                              uint4* __restrict__ out) {
    int idx = blockIdx.x * blockDim.x + threadIdx.x;
    if (idx >= 12 * 1024) return;
    int m = idx >> 10;
    int l = m >> 2, w = m & 3;
    const float* B = (w == 0 ? Wq : w == 1 ? Wk : w == 2 ? Wv : Wo) + l * 4096;
    int rest = idx & 1023;
    int lane = rest & 31, nt = (rest >> 5) & 7, kc = rest >> 8;
    int col = nt * 8 + (lane >> 2);
    int kr = kc * 16 + (lane & 3) * 2;
    float f0 = B[(kr    ) * 64 + col];
    float f1 = B[(kr + 1) * 64 + col];
    float f2 = B[(kr + 8) * 64 + col];
    float f3 = B[(kr + 9) * 64 + col];
    unsigned h0, l0, h1, l1;
    split2(f0, f1, h0, l0);
    split2(f2, f3, h1, l1);
    out[idx] = make_uint4(h0, h1, l0, l1);
}

// ------- fused GEMM: main GEMM + (bias|gate) + LN + in-register QKV GEMMs --
template <int EPI>
__global__ __launch_bounds__(128)
void gemm_fused_kernel(const float* __restrict__ A, const uint4* __restrict__ Bp,
                       float* __restrict__ O0,
                       const float* __restrict__ bias_gw,
                       const float* __restrict__ gb,
                       const float* __restrict__ res,
                       const float* __restrict__ x0p,
                       const float* __restrict__ lns,
                       const float* __restrict__ lnb,
                       const uint4* __restrict__ Bqkv,
                       float* __restrict__ Oq,
                       int M, int K, int KC) {
    __shared__ float sA[64 * 32];
    const int tid = threadIdx.x, warp = tid >> 5, lane = tid & 31;
    const int rowBase = blockIdx.x * 64;
    const int nStages = (KC + 1) >> 1;

    float acc[8][4];
#pragma unroll
    for (int nt = 0; nt < 8; ++nt)
#pragma unroll
        for (int j = 0; j < 4; ++j) acc[nt][j] = 0.f;

    const int cr0 = warp * 16 + (lane >> 2);
    const int cr1 = cr0 + 8;
    const int sw0 = (cr0 & 3) << 3;
    const int sw1 = (cr1 & 3) << 3;

    float rbuf[16];

#define LOADSTAGE(ST)                                                          \
    do {                                                                       \
        int cBase = (ST) * 32;                                                 \
        int gc = cBase + lane;                                                 \
        bool cok = gc < K;                                                     \
        _Pragma("unroll")                                                      \
        for (int i = 0; i < 16; ++i) {                                         \
            int gr = rowBase + i * 4 + warp;                                   \
            rbuf[i] = (gr < M && cok) ? __ldg(A + (long)gr * K + gc) : 0.f;    \
        }                                                                      \
    } while (0)

    LOADSTAGE(0);
    for (int st = 0; st < nStages; ++st) {
#pragma unroll
        for (int i = 0; i < 16; ++i) {
            int rr = i * 4 + warp;
            sA[rr * 32 + (lane ^ ((rr & 3) << 3))] = rbuf[i];
        }
        __syncthreads();
        if (st + 1 < nStages) LOADSTAGE(st + 1);
#pragma unroll
        for (int half = 0; half < 2; ++half) {
            int kc = st * 2 + half;
            if (kc < KC) {
                int c0 = half * 16 + (lane & 3) * 2;
                float2 fA = *(const float2*)&sA[cr0 * 32 + ((c0    ) ^ sw0)];
                float2 fB = *(const float2*)&sA[cr1 * 32 + ((c0    ) ^ sw1)];
                float2 fC = *(const float2*)&sA[cr0 * 32 + ((c0 + 8) ^ sw0)];
                float2 fD = *(const float2*)&sA[cr1 * 32 + ((c0 + 8) ^ sw1)];
                unsigned ahi[4], alo[4];
                split2(fA.x, fA.y, ahi[0], alo[0]);
                split2(fB.x, fB.y, ahi[1], alo[1]);
                split2(fC.x, fC.y, ahi[2], alo[2]);
                split2(fD.x, fD.y, ahi[3], alo[3]);
                const uint4* bp = Bp + (size_t)kc * 256 + lane;
#pragma unroll
                for (int nt = 0; nt < 8; ++nt) {
                    uint4 b = __ldg(&bp[nt * 32]);
                    mma16816(acc[nt], ahi, b.x, b.y);
                    mma16816(acc[nt], alo, b.x, b.y);
                    mma16816(acc[nt], ahi, b.z, b.w);
                }
            }
        }
        __syncthreads();
    }
#undef LOADSTAGE

    const int cbase = (lane & 3) * 2;
    const int gr[2] = { rowBase + cr0, rowBase + cr1 };
    float hv[2][8][2];          // row values in A-fragment layout
    float sum[2] = {0.f, 0.f}, sq[2] = {0.f, 0.f};

    if (EPI == 1) {
        // embedding: bias add, store x0, LN -> hv
#pragma unroll
        for (int f = 0; f < 2; ++f)
#pragma unroll
            for (int nt = 0; nt < 8; ++nt) {
                int cc = nt * 8 + cbase;
                float a0 = acc[nt][2 * f]     + bias_gw[cc];
                float a1 = acc[nt][2 * f + 1] + bias_gw[cc + 1];
                hv[f][nt][0] = a0; hv[f][nt][1] = a1;
                sum[f] += a0 + a1;
                sq[f]  += a0 * a0 + a1 * a1;
                if (gr[f] < M)
                    *(float2*)(O0 + (long)gr[f] * 64 + cc) = make_float2(a0, a1);
            }
    } else {
        // EPI 2: gated residual + alpha mix
        const float* gw = bias_gw;
        float rr[2][8][2], zz[2][8][2];
        float s[2] = {0.f, 0.f};
#pragma unroll
        for (int f = 0; f < 2; ++f) {
            bool ok = gr[f] < M;
#pragma unroll
            for (int nt = 0; nt < 8; ++nt) {
                int cc = nt * 8 + cbase;
                float2 rv = ok ? *(const float2*)(res + (long)gr[f] * 64 + cc)
                               : make_float2(0.f, 0.f);
                float2 zv = ok ? *(const float2*)(x0p + (long)gr[f] * 64 + cc)
                               : make_float2(0.f, 0.f);
                rr[f][nt][0] = rv.x; rr[f][nt][1] = rv.y;
                zz[f][nt][0] = zv.x; zz[f][nt][1] = zv.y;
                float o0 = acc[nt][2 * f], o1 = acc[nt][2 * f + 1];
                s[f] += o0 * gw[cc]        + o1 * gw[cc + 1]
                      + rv.x * gw[64 + cc] + rv.y * gw[65 + cc]
                      + (o0 - rv.x) * gw[128 + cc] + (o1 - rv.y) * gw[129 + cc];
            }
        }
#pragma unroll
        for (int o = 1; o <= 2; o <<= 1) {
            s[0] += __shfl_xor_sync(~0u, s[0], o);
            s[1] += __shfl_xor_sync(~0u, s[1], o);
        }
#pragma unroll
        for (int f = 0; f < 2; ++f) {
            float g = 1.f / (1.f + __expf(-(s[f] + gb[0])));
#pragma unroll
            for (int nt = 0; nt < 8; ++nt) {
                float o0 = acc[nt][2 * f], o1 = acc[nt][2 * f + 1];
                float n0 = ALPHA * (g * o0 + (1.f - g) * rr[f][nt][0])
                         + (1.f - ALPHA) * zz[f][nt][0];
                float n1 = ALPHA * (g * o1 + (1.f - g) * rr[f][nt][1])
                         + (1.f - ALPHA) * zz[f][nt][1];
                hv[f][nt][0] = n0; hv[f][nt][1] = n1;
                sum[f] += n0 + n1;
                sq[f]  += n0 * n0 + n1 * n1;
                if (gr[f] < M) {
                    int cc = nt * 8 + cbase;
                    *(float2*)(O0 + (long)gr[f] * 64 + cc) = make_float2(n0, n1);
                }
            }
        }
    }

    if (lns) {
        // LayerNorm in registers (quad reduction over the 4 lanes of a row)
#pragma unroll
        for (int o = 1; o <= 2; o <<= 1) {
            sum[0] += __shfl_xor_sync(~0u, sum[0], o);
            sum[1] += __shfl_xor_sync(~0u, sum[1], o);
            sq[0]  += __shfl_xor_sync(~0u, sq[0],  o);
            sq[1]  += __shfl_xor_sync(~0u, sq[1],  o);
        }
#pragma unroll
        for (int f = 0; f < 2; ++f) {
            float mu = sum[f] * (1.f / 64.f);
            float var = sq[f] * (1.f / 64.f) - mu * mu;
            float rstd = rsqrtf(var + 1e-5f);
#pragma unroll
            for (int nt = 0; nt < 8; ++nt) {
                int cc = nt * 8 + cbase;
                hv[f][nt][0] = (hv[f][nt][0] - mu) * rstd * lns[cc]     + lnb[cc];
                hv[f][nt][1] = (hv[f][nt][1] - mu) * rstd * lns[cc + 1] + lnb[cc + 1];
            }
        }
    }

    if (Bqkv) {
        // in-register QKV GEMMs: hv already sits in mma A-fragment layout
#pragma unroll
        for (int m = 0; m < 3; ++m) {
            float a2[8][4];
#pragma unroll
            for (int nt = 0; nt < 8; ++nt)
#pragma unroll
                for (int j = 0; j < 4; ++j) a2[nt][j] = 0.f;
#pragma unroll
            for (int kc = 0; kc < 4; ++kc) {
                unsigned ahi[4], alo[4];
                split2(hv[0][2*kc][0],   hv[0][2*kc][1],   ahi[0], alo[0]);
                split2(hv[1][2*kc][0],   hv[1][2*kc][1],   ahi[1], alo[1]);
                split2(hv[0][2*kc+1][0], hv[0][2*kc+1][1], ahi[2], alo[2]);
                split2(hv[1][2*kc+1][0], hv[1][2*kc+1][1], ahi[3], alo[3]);
                const uint4* bm = Bqkv + (size_t)m * 1024 + kc * 256 + lane;
#pragma unroll
                for (int nt = 0; nt < 8; ++nt) {
                    uint4 b = __ldg(&bm[nt * 32]);
                    mma16816(a2[nt], ahi, b.x, b.y);
                    mma16816(a2[nt], alo, b.x, b.y);
                    mma16816(a2[nt], ahi, b.z, b.w);
                }
            }
            if (m == 0) {
                // q in fp32
#pragma unroll
                for (int f = 0; f < 2; ++f) {
                    if (gr[f] >= M) continue;
#pragma unroll
                    for (int nt = 0; nt < 8; ++nt) {
                        int cc = nt * 8 + cbase;
                        *(float2*)(Oq + (long)gr[f] * 64 + cc) =
                            make_float2(a2[nt][2 * f], a2[nt][2 * f + 1]);
                    }
                }
            } else {
                // k/v packed half2
                unsigned* O2 = (m == 1) ? g_k2 : g_v2;
#pragma unroll
                for (int f = 0; f < 2; ++f) {
                    if (gr[f] >= M) continue;
#pragma unroll
                    for (int nt = 0; nt < 8; ++nt) {
                        __half2 hh = __floats2half2_rn(a2[nt][2 * f],
                                                       a2[nt][2 * f + 1]);
                        O2[(long)gr[f] * 32 + nt * 4 + (lane & 3)] =
                            *reinterpret_cast<unsigned*>(&hh);
                    }
                }
            }
        }
    }
}

// ---------------- CSR construction ----------------
__global__ void zero_deg_kernel() {
    int i = blockIdx.x * blockDim.x + threadIdx.x;
    if (i < NN) g_deg[i] = 0;
}

__global__ void hist_kernel(const int* __restrict__ ei) {
    int e = blockIdx.x * blockDim.x + threadIdx.x;
    if (e < EE) atomicAdd(&g_deg[ei[EE + e]], 1);
}

__global__ void scan_kernel() {
    __shared__ int ssum[1024];
    const int t = threadIdx.x;
    const int CHUNK = (NN + 1023) / 1024;
    int beg = t * CHUNK;
    int end = beg + CHUNK; if (end > NN) end = NN;
    int s = 0;
    for (int i = beg; i < end; ++i) s += g_deg[i];
    ssum[t] = s;
    __syncthreads();
    for (int d = 1; d < 1024; d <<= 1) {
        int v = (t >= d) ? ssum[t - d] : 0;
        __syncthreads();
        ssum[t] += v;
        __syncthreads();
    }
    int run = (t == 0) ? 0 : ssum[t - 1];
    for (int i = beg; i < end; ++i) {
        g_off[i] = run;
        g_pos[i] = run;
        run += g_deg[i];
    }
    if (t == 1023) g_off[NN] = ssum[1023];
}

__global__ void fill_kernel(const int* __restrict__ ei) {
    int e = blockIdx.x * blockDim.x + threadIdx.x;
    if (e < EE) {
        int d = ei[EE + e];
        int p = atomicAdd(&g_pos[d], 1);
        g_csr[p] = ei[e];
    }
}

// ---- fused edge attention: half-warp per edge, 4 dims/lane, 2-shfl dot ----
__global__ __launch_bounds__(256)
void attn_kernel() {
    int warp = (blockIdx.x * blockDim.x + threadIdx.x) >> 5;
    int lane = threadIdx.x & 31;
    if (warp >= NN) return;
    const int sub = lane >> 4;       // which half-warp (edge slot)
    const int sl  = lane & 15;       // dims 4*sl .. 4*sl+3; head = sl>>2
    float4 q4 = ((const float4*)(g_q + (size_t)warp * 64))[sl];
    q4.x *= 0.25f; q4.y *= 0.25f; q4.z *= 0.25f; q4.w *= 0.25f;
    const int beg = g_off[warp], end = g_off[warp + 1];
    const int steps = (end - beg + 1) >> 1;
    float l = 0.f, a0 = 0.f, a1 = 0.f, a2 = 0.f, a3 = 0.f;
    float lB = 0.f, b0 = 0.f, b1 = 0.f, b2 = 0.f, b3 = 0.f;

    int t = 0;
    for (; t + 1 < steps; t += 2) {
        int eA = beg + 2 * t + sub;
        int eB = eA + 2;
        bool vA = eA < end, vB = eB < end;
        int sA = g_csr[vA ? eA : beg];
        int sB = g_csr[vB ? eB : beg];
        uint2 kwA = *(const uint2*)(g_k2 + (size_t)sA * 32 + sl * 2);
        uint2 vwA = *(const uint2*)(g_v2 + (size_t)sA * 32 + sl * 2);
        uint2 kwB = *(const uint2*)(g_k2 + (size_t)sB * 32 + sl * 2);
        uint2 vwB = *(const uint2*)(g_v2 + (size_t)sB * 32 + sl * 2);
        float2 kA0 = h2f2(kwA.x), kA1 = h2f2(kwA.y);
        float2 kB0 = h2f2(kwB.x), kB1 = h2f2(kwB.y);
        float dA = q4.x * kA0.x + q4.y * kA0.y + q4.z * kA1.x + q4.w * kA1.y;
        float dB = q4.x * kB0.x + q4.y * kB0.y + q4.z * kB1.x + q4.w * kB1.y;
#pragma unroll
        for (int o = 1; o <= 2; o <<= 1) {
            dA += __shfl_xor_sync(~0u, dA, o);
            dB += __shfl_xor_sync(~0u, dB, o);
        }
        float pA = vA ? __expf(dA) : 0.f;
        float pB = vB ? __expf(dB) : 0.f;
        float2 vA0 = h2f2(vwA.x), vA1 = h2f2(vwA.y);
        float2 vB0 = h2f2(vwB.x), vB1 = h2f2(vwB.y);
        l  += pA;  a0 += pA * vA0.x; a1 += pA * vA0.y;
                   a2 += pA * vA1.x; a3 += pA * vA1.y;
        lB += pB;  b0 += pB * vB0.x; b1 += pB * vB0.y;
                   b2 += pB * vB1.x; b3 += pB * vB1.y;
    }
    if (t < steps) {
        int eA = beg + 2 * t + sub;
        bool vA = eA < end;
        int sA = g_csr[vA ? eA : beg];
        uint2 kwA = *(const uint2*)(g_k2 + (size_t)sA * 32 + sl * 2);
        uint2 vwA = *(const uint2*)(g_v2 + (size_t)sA * 32 + sl * 2);
        float2 kA0 = h2f2(kwA.x), kA1 = h2f2(kwA.y);
        float dA = q4.x * kA0.x + q4.y * kA0.y + q4.z * kA1.x + q4.w * kA1.y;
#pragma unroll
        for (int o = 1; o <= 2; o <<= 1) dA += __shfl_xor_sync(~0u, dA, o);
        float pA = vA ? __expf(dA) : 0.f;
        float2 vA0 = h2f2(vwA.x), vA1 = h2f2(vwA.y);
        l += pA; a0 += pA * vA0.x; a1 += pA * vA0.y;
                 a2 += pA * vA1.x; a3 += pA * vA1.y;
    }
    l += lB; a0 += b0; a1 += b1; a2 += b2; a3 += b3;
    // combine the two half-warp partial sums
    l  += __shfl_xor_sync(~0u, l,  16);
    a0 += __shfl_xor_sync(~0u, a0, 16);
    a1 += __shfl_xor_sync(~0u, a1, 16);
    a2 += __shfl_xor_sync(~0u, a2, 16);
    a3 += __shfl_xor_sync(~0u, a3, 16);
    if (sub == 0) {
        float inv = 1.f / (l + 1e-9f);
        ((float4*)(g_agg + (size_t)warp * 64))[sl] =
            make_float4(a0 * inv, a1 * inv, a2 * inv, a3 * inv);
    }
}

// ---------------- launch ----------------
extern "C" void kernel_launch(void* const* d_in, const int* in_sizes, int n_in,
                              void* d_out, int out_size) {
    const float* nodes = (const float*)d_in[0];
    const int*   ei    = (const int*)  d_in[1];
    const float* emb_W = (const float*)d_in[2];
    const float* emb_b = (const float*)d_in[3];
    const float* ln_s  = (const float*)d_in[4];
    const float* ln_b  = (const float*)d_in[5];
    const float* Wq    = (const float*)d_in[6];
    const float* Wk    = (const float*)d_in[7];
    const float* Wv    = (const float*)d_in[8];
    const float* Wo    = (const float*)d_in[9];
    const float* gW    = (const float*)d_in[10];
    const float* gb    = (const float*)d_in[11];
    float* out = (float*)d_out;

    float *px0, *px, *pagg, *pq;
    uint4 *pBemb, *pBw;
    cudaGetSymbolAddress((void**)&px0,  g_x0);
    cudaGetSymbolAddress((void**)&px,   g_x);
    cudaGetSymbolAddress((void**)&pagg, g_agg);
    cudaGetSymbolAddress((void**)&pq,   g_q);
    cudaGetSymbolAddress((void**)&pBemb, g_Bemb);
    cudaGetSymbolAddress((void**)&pBw,   g_Bw);

    const int gemmGrid = (NN + 63) / 64;     // 1563
    const int warpGrid = (NN + 7) / 8;

    // launches 1-3
    pack_b_kernel<<<(KC_EMB * 256 + 255) / 256, 256>>>(emb_W, pBemb, F_IN, KC_EMB);
    pack_w_kernel<<<(12 * 1024 + 255) / 256, 256>>>(Wq, Wk, Wv, Wo, pBw);
    zero_deg_kernel<<<(NN + 255) / 256, 256>>>();
    // launch 4 (ncu capture): embedding GEMM + bias + LN0 + QKV0, all fused
    gemm_fused_kernel<1><<<gemmGrid, 128>>>(
        nodes, pBemb, px0, emb_b, nullptr, nullptr, nullptr,
        ln_s, ln_b, pBw, pq, NN, F_IN, KC_EMB);
    // CSR build
    hist_kernel<<<(EE + 255) / 256, 256>>>(ei);
    scan_kernel<<<1, 1024>>>();
    fill_kernel<<<(EE + 255) / 256, 256>>>(ei);

    for (int l = 0; l < DEPTH; ++l) {
        attn_kernel<<<warpGrid, 256>>>();   // q,k,v -> agg
        const float* res = (l == 0) ? px0 : px;
        float* dst = (l == DEPTH - 1) ? out : px;
        const float* nls = (l == DEPTH - 1) ? nullptr : ln_s + (l + 1) * 64;
        const float* nlb = (l == DEPTH - 1) ? nullptr : ln_b + (l + 1) * 64;
        const uint4* bqkv = (l == DEPTH - 1) ? nullptr
                                             : pBw + (size_t)(l + 1) * 4 * 1024;
        // Wo GEMM + gate + alpha mix + next LN + next QKV, all fused
        gemm_fused_kernel<2><<<gemmGrid, 128>>>(
            pagg, pBw + (size_t)(l * 4 + 3) * 1024, dst,
            gW + l * 192, gb + l, res, px0, nls, nlb,
            bqkv, pq, NN, 64, 4);
    }
}